// round 11
// baseline (speedup 1.0000x reference)
#include <cuda_runtime.h>
#include <cuda_fp16.h>
#include <cstdint>
#include <cstddef>

// Problem constants
#define NBATCH 4
#define NTOK   2048
#define NCH    1024
#define NHEAD  16
#define NHD    64
#define NROWS  8192   // NBATCH*NTOK

// ---------------- scratch (device globals; no allocs allowed) ----------------
__device__ __half g_xn[(size_t)NROWS * NCH];
__device__ __half g_q [(size_t)NROWS * NCH];        // [b][h][t][d]
__device__ __half g_k [(size_t)NROWS * NCH];        // [b][h][t][d]
__device__ __half g_vT[(size_t)NROWS * NCH];        // [b][h][d][t]
__device__ __half g_y [(size_t)NROWS * NCH];
__device__ __half g_w16[4][(size_t)NCH * NCH];

// ---------------- PTX helpers ----------------
__device__ __forceinline__ uint32_t smem_u32(const void* p) {
    return (uint32_t)__cvta_generic_to_shared(p);
}
__device__ __forceinline__ void ldm_x4(uint32_t* r, const void* p) {
    uint32_t a = smem_u32(p);
    asm volatile("ldmatrix.sync.aligned.m8n8.x4.shared.b16 {%0,%1,%2,%3}, [%4];"
                 : "=r"(r[0]), "=r"(r[1]), "=r"(r[2]), "=r"(r[3]) : "r"(a));
}
__device__ __forceinline__ void mma_16816(float* c, const uint32_t* a, const uint32_t* b) {
    asm volatile("mma.sync.aligned.m16n8k16.row.col.f32.f16.f16.f32 "
                 "{%0,%1,%2,%3}, {%4,%5,%6,%7}, {%8,%9}, {%0,%1,%2,%3};"
                 : "+f"(c[0]), "+f"(c[1]), "+f"(c[2]), "+f"(c[3])
                 : "r"(a[0]), "r"(a[1]), "r"(a[2]), "r"(a[3]),
                   "r"(b[0]), "r"(b[1]));
}
__device__ __forceinline__ void cpa16(uint32_t smem, const void* g) {
    asm volatile("cp.async.cg.shared.global [%0], [%1], 16;"
                 :: "r"(smem), "l"(g) : "memory");
}
__device__ __forceinline__ void cpa_commit() { asm volatile("cp.async.commit_group;" ::: "memory"); }
__device__ __forceinline__ void cpa_wait0()  { asm volatile("cp.async.wait_group 0;" ::: "memory"); }
__device__ __forceinline__ void cpa_wait1()  { asm volatile("cp.async.wait_group 1;" ::: "memory"); }

__device__ __forceinline__ uint32_t f2h2u(float a, float b) {
    __half2 h = __floats2half2_rn(a, b);
    return *reinterpret_cast<uint32_t*>(&h);
}
__device__ __forceinline__ float negInf() { return __int_as_float(0xff800000); }
__device__ __forceinline__ float ex2(float x) {
    float y;
    asm("ex2.approx.ftz.f32 %0, %1;" : "=f"(y) : "f"(x));
    return y;
}

// ---------------- kernel 1: weight fp32 -> fp16 ----------------
__global__ __launch_bounds__(256) void cvt_kernel(const float* __restrict__ w0,
                                                  const float* __restrict__ w1,
                                                  const float* __restrict__ w2,
                                                  const float* __restrict__ w3) {
    const int sel = blockIdx.x >> 10;
    const float* src = (sel == 0) ? w0 : (sel == 1) ? w1 : (sel == 2) ? w2 : w3;
    __half* dst = g_w16[sel];
    size_t i = ((size_t)(blockIdx.x & 1023) * blockDim.x + threadIdx.x) * 4;
    float4 v = *(const float4*)(src + i);
    __half2* dd = (__half2*)(dst + i);
    dd[0] = __floats2half2_rn(v.x, v.y);
    dd[1] = __floats2half2_rn(v.z, v.w);
}

// ---------------- kernel 2: LayerNorm ----------------
__global__ __launch_bounds__(256) void ln_kernel(const float* __restrict__ x,
                                                 const float* __restrict__ gamma,
                                                 const float* __restrict__ beta) {
    __shared__ float redS[8], redQ[8];
    const int row = blockIdx.x;
    const int tid = threadIdx.x;
    float4 v = ((const float4*)(x + (size_t)row * NCH))[tid];
    float s = v.x + v.y + v.z + v.w;
    float q = v.x * v.x + v.y * v.y + v.z * v.z + v.w * v.w;
    #pragma unroll
    for (int o = 16; o > 0; o >>= 1) {
        s += __shfl_xor_sync(0xffffffffu, s, o);
        q += __shfl_xor_sync(0xffffffffu, q, o);
    }
    if ((tid & 31) == 0) { redS[tid >> 5] = s; redQ[tid >> 5] = q; }
    __syncthreads();
    float S = 0.f, Q = 0.f;
    #pragma unroll
    for (int i = 0; i < 8; i++) { S += redS[i]; Q += redQ[i]; }
    const float mu = S * (1.0f / NCH);
    const float var = Q * (1.0f / NCH) - mu * mu;
    const float rstd = rsqrtf(var + 1e-5f);
    float4 gv = ((const float4*)gamma)[tid];
    float4 bv = ((const float4*)beta)[tid];
    __half2 h0 = __floats2half2_rn((v.x - mu) * rstd * gv.x + bv.x,
                                   (v.y - mu) * rstd * gv.y + bv.y);
    __half2 h1 = __floats2half2_rn((v.z - mu) * rstd * gv.z + bv.z,
                                   (v.w - mu) * rstd * gv.w + bv.w);
    __half2* dst = (__half2*)(g_xn + (size_t)row * NCH + tid * 4);
    dst[0] = h0; dst[1] = h1;
}

// ---------------- kernel 3: HMMA GEMM, block 128x128, 4 warps (2x2 of 64x64) --
#define GP2 72
#define G_ST (128 * GP2)                       // per-operand stage halfs
#define GEMM_SMEM (6 * G_ST * 2)               // 3 stages x 2 operands = 110592 B

__global__ __launch_bounds__(128, 1) void gemm_hmma(float* __restrict__ outF, int qkv) {
    extern __shared__ __half sm[];
    __half* As[3] = { sm, sm + G_ST, sm + 2 * G_ST };
    __half* Bs[3] = { sm + 3 * G_ST, sm + 4 * G_ST, sm + 5 * G_ST };

    int wsel, bN;
    const __half* __restrict__ A;
    if (qkv) { wsel = blockIdx.x >> 3; bN = (blockIdx.x & 7) * 128; A = g_xn; }
    else     { wsel = 3;               bN = blockIdx.x * 128;       A = g_y;  }
    const __half* __restrict__ Bw = g_w16[wsel];
    const int bM = blockIdx.y * 128;

    const int tid = threadIdx.x;
    const int lane = tid & 31, warp = tid >> 5;
    const int wm = warp >> 1, wn = warp & 1;       // 2x2 warps, warp tile 64x64

    float acc[4][8][4];
    #pragma unroll
    for (int i = 0; i < 4; i++)
        #pragma unroll
        for (int j = 0; j < 8; j++)
            #pragma unroll
            for (int e = 0; e < 4; e++) acc[i][j][e] = 0.f;

    auto load_stage = [&](int slot, int k0) {
        #pragma unroll
        for (int i = 0; i < 8; i++) {
            const int idx = tid + i * 128;
            const int row = idx >> 3, c = idx & 7;
            cpa16(smem_u32(As[slot] + row * GP2 + c * 8),
                  A + (size_t)(bM + row) * NCH + k0 + c * 8);
            cpa16(smem_u32(Bs[slot] + row * GP2 + c * 8),
                  Bw + (size_t)(bN + row) * NCH + k0 + c * 8);
        }
        cpa_commit();
    };

    load_stage(0, 0);
    load_stage(1, 64);

    const int KT = NCH / 64;
    for (int kt = 0; kt < KT; kt++) {
        if (kt < KT - 1) cpa_wait1(); else cpa_wait0();
        __syncthreads();
        if (kt + 2 < KT) load_stage((kt + 2) % 3, (kt + 2) * 64);

        const __half* as = As[kt % 3];
        const __half* bs = Bs[kt % 3];
        #pragma unroll
        for (int kk = 0; kk < 64; kk += 16) {
            const int cA = kk + 8 * (lane >> 4);
            uint32_t af[4][4];
            const int rA = wm * 64 + (lane & 15);
            #pragma unroll
            for (int mt = 0; mt < 4; mt++)
                ldm_x4(af[mt], as + (rA + mt * 16) * GP2 + cA);
            uint32_t bf[8][2];
            const int rB = wn * 64 + (lane & 15);
            #pragma unroll
            for (int p = 0; p < 4; p++) {
                uint32_t t4[4];
                ldm_x4(t4, bs + (rB + p * 16) * GP2 + cA);
                bf[p * 2][0]     = t4[0]; bf[p * 2][1]     = t4[2];
                bf[p * 2 + 1][0] = t4[1]; bf[p * 2 + 1][1] = t4[3];
            }
            #pragma unroll
            for (int mt = 0; mt < 4; mt++)
                #pragma unroll
                for (int nt = 0; nt < 8; nt++)
                    mma_16816(acc[mt][nt], af[mt], bf[nt]);
        }
    }

    #pragma unroll
    for (int mt = 0; mt < 4; mt++) {
        #pragma unroll
        for (int nt = 0; nt < 8; nt++) {
            const int r0 = bM + wm * 64 + mt * 16 + (lane >> 2);
            const int c0 = bN + wn * 64 + nt * 8 + (lane & 3) * 2;
            const float* v = acc[mt][nt];
            #pragma unroll
            for (int half_ : {0, 1}) {
                const int r = r0 + half_ * 8;
                const float v0 = v[half_ * 2], v1 = v[half_ * 2 + 1];
                const int b = r >> 11, t = r & 2047;
                if (wsel == 3) {
                    float2* dst = (float2*)(outF + (size_t)r * NCH + c0);
                    *dst = make_float2(v0, v1);
                } else if (wsel == 2) {
                    const int h = c0 >> 6, d = c0 & 63;
                    __half* base = g_vT + (((size_t)b * NHEAD + h) * NHD + d) * NTOK + t;
                    base[0]    = __float2half_rn(v0);
                    base[NTOK] = __float2half_rn(v1);
                } else {
                    const int h = c0 >> 6, d = c0 & 63;
                    __half* base = ((wsel == 0) ? g_q : g_k) +
                                   (((size_t)b * NHEAD + h) * NTOK + t) * NHD + d;
                    *(__half2*)base = __floats2half2_rn(v0, v1);
                }
            }
        }
    }
}

// ---------------- kernel 4: flash attention, Br=128 (8 warps x 16 rows), Bc=64 -
#define AP 72   // smem pitch (144B), conflict-free ldmatrix
#define AQ_ST  (128 * AP)                    // Q: 128 rows
#define AKV_ST (64 * AP)                     // K/V: 64 rows per buffer
#define ATTN_SMEM ((AQ_ST + 4 * AKV_ST) * 2) // 55296 B

__global__ __launch_bounds__(256, 1) void attn_kernel() {
    extern __shared__ __half asm_[];
    __half* Qs    = asm_;
    __half* Ks[2] = { asm_ + AQ_ST,               asm_ + AQ_ST + AKV_ST };
    __half* Vs[2] = { asm_ + AQ_ST + 2 * AKV_ST,  asm_ + AQ_ST + 3 * AKV_ST };

    const int qt = gridDim.x - 1 - blockIdx.x;   // heaviest blocks first
    const int bh = blockIdx.y;                   // 0..63
    const int tid = threadIdx.x;
    const int lane = tid & 31, warp = tid >> 5;  // 8 warps
    const int q0 = qt * 128;

    const __half* __restrict__ Qg = g_q  + (size_t)bh * NTOK * NHD;
    const __half* __restrict__ Kg = g_k  + (size_t)bh * NTOK * NHD;
    const __half* __restrict__ Vg = g_vT + (size_t)bh * NHD * NTOK;

    // prologue: Q tile (128x64) + K/V tile 0 via cp.async (one group)
    #pragma unroll
    for (int i = 0; i < 4; i++) {
        const int idx = tid + i * 256;
        const int r = idx >> 3, ch = (idx & 7) * 8;
        cpa16(smem_u32(&Qs[r * AP + ch]), Qg + (size_t)(q0 + r) * NHD + ch);
    }
    #pragma unroll
    for (int i = 0; i < 2; i++) {
        const int idx = tid + i * 256;
        const int r = idx >> 3, ch = (idx & 7) * 8;
        cpa16(smem_u32(&Ks[0][r * AP + ch]), Kg + (size_t)r * NHD + ch);
        cpa16(smem_u32(&Vs[0][r * AP + ch]), Vg + (size_t)r * NTOK + ch);
    }
    cpa_commit();
    cpa_wait0();
    __syncthreads();

    // Q fragments: 16 rows/warp, pre-scaled by 1/8 * log2(e) (base-2 softmax)
    uint32_t qf[4][4];
    {
        const int rA = warp * 16 + (lane & 15);
        const int cA = 8 * (lane >> 4);
        const __half2 sc = __float2half2_rn(0.125f * 1.44269504f);
        #pragma unroll
        for (int kc = 0; kc < 4; kc++) {
            ldm_x4(qf[kc], &Qs[rA * AP + kc * 16 + cA]);
            #pragma unroll
            for (int e = 0; e < 4; e++) {
                __half2 h = *reinterpret_cast<__half2*>(&qf[kc][e]);
                h = __hmul2(h, sc);
                qf[kc][e] = *reinterpret_cast<uint32_t*>(&h);
            }
        }
    }

    float m0 = negInf(), m1 = negInf();
    float l0 = 0.f, l1 = 0.f;
    float o[8][4];
    #pragma unroll
    for (int nt = 0; nt < 8; nt++)
        #pragma unroll
        for (int e = 0; e < 4; e++) o[nt][e] = 0.f;

    const int rP = lane & 15;            // x4 ldmatrix row within 16-row pair
    const int cP = 8 * (lane >> 4);      // k-half select
    const int jmax = 2 * qt + 1;         // KV tiles of 64 keys

    for (int j = 0; j <= jmax; j++) {
        const int buf = j & 1;
        if (j < jmax) {
            const int nb = buf ^ 1;
            #pragma unroll
            for (int i = 0; i < 2; i++) {
                const int idx = tid + i * 256;
                const int r = idx >> 3, ch = (idx & 7) * 8;
                cpa16(smem_u32(&Ks[nb][r * AP + ch]),
                      Kg + (size_t)((j + 1) * 64 + r) * NHD + ch);
                cpa16(smem_u32(&Vs[nb][r * AP + ch]),
                      Vg + (size_t)r * NTOK + (j + 1) * 64 + ch);
            }
            cpa_commit();
        }

        // S = (Q*scale) @ K^T : 16x64 per warp
        float s[8][4];
        #pragma unroll
        for (int nt = 0; nt < 8; nt++)
            #pragma unroll
            for (int e = 0; e < 4; e++) s[nt][e] = 0.f;
        #pragma unroll
        for (int kc = 0; kc < 4; kc++) {
            #pragma unroll
            for (int p = 0; p < 4; p++) {
                uint32_t t4[4];
                ldm_x4(t4, &Ks[buf][(p * 16 + rP) * AP + kc * 16 + cP]);
                uint32_t be[2] = { t4[0], t4[2] };
                uint32_t bo[2] = { t4[1], t4[3] };
                mma_16816(s[p * 2],     qf[kc], be);
                mma_16816(s[p * 2 + 1], qf[kc], bo);
            }
        }

        // causal mask on the last two tiles (global index compare)
        if (j >= 2 * qt) {
            const int rl = q0 + warp * 16 + (lane >> 2);
            const int cb = j * 64 + (lane & 3) * 2;
            #pragma unroll
            for (int nt = 0; nt < 8; nt++) {
                const int c0 = cb + nt * 8;
                if (c0     > rl)     s[nt][0] = -1e30f;
                if (c0 + 1 > rl)     s[nt][1] = -1e30f;
                if (c0     > rl + 8) s[nt][2] = -1e30f;
                if (c0 + 1 > rl + 8) s[nt][3] = -1e30f;
            }
        }

        // online softmax in base 2 (rows r and r+8 per lane-group)
        float mx0 = -3.0e38f, mx1 = -3.0e38f;
        #pragma unroll
        for (int nt = 0; nt < 8; nt++) {
            mx0 = fmaxf(mx0, fmaxf(s[nt][0], s[nt][1]));
            mx1 = fmaxf(mx1, fmaxf(s[nt][2], s[nt][3]));
        }
        mx0 = fmaxf(mx0, __shfl_xor_sync(0xffffffffu, mx0, 1));
        mx0 = fmaxf(mx0, __shfl_xor_sync(0xffffffffu, mx0, 2));
        mx1 = fmaxf(mx1, __shfl_xor_sync(0xffffffffu, mx1, 1));
        mx1 = fmaxf(mx1, __shfl_xor_sync(0xffffffffu, mx1, 2));
        const float mn0 = fmaxf(m0, mx0), mn1 = fmaxf(m1, mx1);
        const float cor0 = ex2(m0 - mn0), cor1 = ex2(m1 - mn1);
        m0 = mn0; m1 = mn1;
        float sum0 = 0.f, sum1 = 0.f;
        #pragma unroll
        for (int nt = 0; nt < 8; nt++) {
            s[nt][0] = ex2(s[nt][0] - mn0); sum0 += s[nt][0];
            s[nt][1] = ex2(s[nt][1] - mn0); sum0 += s[nt][1];
            s[nt][2] = ex2(s[nt][2] - mn1); sum1 += s[nt][2];
            s[nt][3] = ex2(s[nt][3] - mn1); sum1 += s[nt][3];
        }
        sum0 += __shfl_xor_sync(0xffffffffu, sum0, 1);
        sum0 += __shfl_xor_sync(0xffffffffu, sum0, 2);
        sum1 += __shfl_xor_sync(0xffffffffu, sum1, 1);
        sum1 += __shfl_xor_sync(0xffffffffu, sum1, 2);
        l0 = l0 * cor0 + sum0;
        l1 = l1 * cor1 + sum1;
        #pragma unroll
        for (int nt = 0; nt < 8; nt++) {
            o[nt][0] *= cor0; o[nt][1] *= cor0;
            o[nt][2] *= cor1; o[nt][3] *= cor1;
        }

        // P fragments directly from S accumulators
        uint32_t pf[4][4];
        #pragma unroll
        for (int kc = 0; kc < 4; kc++) {
            pf[kc][0] = f2h2u(s[2 * kc][0],     s[2 * kc][1]);
            pf[kc][1] = f2h2u(s[2 * kc][2],     s[2 * kc][3]);
            pf[kc][2] = f2h2u(s[2 * kc + 1][0], s[2 * kc + 1][1]);
            pf[kc][3] = f2h2u(s[2 * kc + 1][2], s[2 * kc + 1][3]);
        }

        // O += P @ V ; V frags via x4 over 16-row pairs
        #pragma unroll
        for (int kc = 0; kc < 4; kc++) {
            #pragma unroll
            for (int p = 0; p < 4; p++) {
                uint32_t t4[4];
                ldm_x4(t4, &Vs[buf][(p * 16 + rP) * AP + kc * 16 + cP]);
                uint32_t be[2] = { t4[0], t4[2] };
                uint32_t bo[2] = { t4[1], t4[3] };
                mma_16816(o[p * 2],     pf[kc], be);
                mma_16816(o[p * 2 + 1], pf[kc], bo);
            }
        }

        if (j < jmax) {
            cpa_wait0();
            __syncthreads();
        }
    }

    // finalize
    const int b = bh >> 4, h = bh & 15;
    const int trow = q0 + warp * 16 + (lane >> 2);
    const float inv0 = 1.0f / l0, inv1 = 1.0f / l1;
    #pragma unroll
    for (int nt = 0; nt < 8; nt++) {
        const int col = h * 64 + nt * 8 + (lane & 3) * 2;
        const size_t base = (size_t)(b * NTOK + trow) * NCH + col;
        *(__half2*)(g_y + base) = __floats2half2_rn(o[nt][0] * inv0, o[nt][1] * inv0);
        *(__half2*)(g_y + base + (size_t)8 * NCH) =
            __floats2half2_rn(o[nt][2] * inv1, o[nt][3] * inv1);
    }
}

// ---------------- launch ----------------
extern "C" void kernel_launch(void* const* d_in, const int* in_sizes, int n_in,
                              void* d_out, int out_size) {
    (void)in_sizes; (void)n_in; (void)out_size;
    const float* x     = (const float*)d_in[0];
    const float* gamma = (const float*)d_in[1];
    const float* beta  = (const float*)d_in[2];

    cudaFuncSetAttribute(gemm_hmma, cudaFuncAttributeMaxDynamicSharedMemorySize, GEMM_SMEM);
    cudaFuncSetAttribute(attn_kernel, cudaFuncAttributeMaxDynamicSharedMemorySize, ATTN_SMEM);

    cvt_kernel<<<4096, 256>>>((const float*)d_in[3], (const float*)d_in[4],
                              (const float*)d_in[5], (const float*)d_in[6]);

    ln_kernel<<<NROWS, 256>>>(x, gamma, beta);

    gemm_hmma<<<dim3(24, 64), 128, GEMM_SMEM>>>(nullptr, 1);        // fused Q/K/V

    attn_kernel<<<dim3(NTOK / 128, NBATCH * NHEAD), 256, ATTN_SMEM>>>();

    gemm_hmma<<<dim3(8, 64), 128, GEMM_SMEM>>>((float*)d_out, 0);   // output proj
}

// round 12
// speedup vs baseline: 1.0831x; 1.0831x over previous
#include <cuda_runtime.h>
#include <cuda_fp16.h>
#include <cstdint>
#include <cstddef>

// Problem constants
#define NBATCH 4
#define NTOK   2048
#define NCH    1024
#define NHEAD  16
#define NHD    64
#define NROWS  8192   // NBATCH*NTOK

// ---------------- scratch (device globals; no allocs allowed) ----------------
__device__ __half g_xn[(size_t)NROWS * NCH];
__device__ __half g_q [(size_t)NROWS * NCH];        // [b][h][t][d]
__device__ __half g_k [(size_t)NROWS * NCH];        // [b][h][t][d]
__device__ __half g_vT[(size_t)NROWS * NCH];        // [b][h][d][t]
__device__ __half g_y [(size_t)NROWS * NCH];
__device__ __half g_w16[4][(size_t)NCH * NCH];

// ---------------- PTX helpers ----------------
__device__ __forceinline__ uint32_t smem_u32(const void* p) {
    return (uint32_t)__cvta_generic_to_shared(p);
}
__device__ __forceinline__ void ldm_x4(uint32_t* r, const void* p) {
    uint32_t a = smem_u32(p);
    asm volatile("ldmatrix.sync.aligned.m8n8.x4.shared.b16 {%0,%1,%2,%3}, [%4];"
                 : "=r"(r[0]), "=r"(r[1]), "=r"(r[2]), "=r"(r[3]) : "r"(a));
}
__device__ __forceinline__ void mma_16816(float* c, const uint32_t* a, const uint32_t* b) {
    asm volatile("mma.sync.aligned.m16n8k16.row.col.f32.f16.f16.f32 "
                 "{%0,%1,%2,%3}, {%4,%5,%6,%7}, {%8,%9}, {%0,%1,%2,%3};"
                 : "+f"(c[0]), "+f"(c[1]), "+f"(c[2]), "+f"(c[3])
                 : "r"(a[0]), "r"(a[1]), "r"(a[2]), "r"(a[3]),
                   "r"(b[0]), "r"(b[1]));
}
__device__ __forceinline__ void cpa16(uint32_t smem, const void* g) {
    asm volatile("cp.async.cg.shared.global [%0], [%1], 16;"
                 :: "r"(smem), "l"(g) : "memory");
}
__device__ __forceinline__ void cpa_commit() { asm volatile("cp.async.commit_group;" ::: "memory"); }
__device__ __forceinline__ void cpa_wait0()  { asm volatile("cp.async.wait_group 0;" ::: "memory"); }
__device__ __forceinline__ void cpa_wait1()  { asm volatile("cp.async.wait_group 1;" ::: "memory"); }

__device__ __forceinline__ uint32_t f2h2u(float a, float b) {
    __half2 h = __floats2half2_rn(a, b);
    return *reinterpret_cast<uint32_t*>(&h);
}
__device__ __forceinline__ float negInf() { return __int_as_float(0xff800000); }
__device__ __forceinline__ float ex2(float x) {
    float y;
    asm("ex2.approx.ftz.f32 %0, %1;" : "=f"(y) : "f"(x));
    return y;
}

// ---------------- kernel 1: weight fp32 -> fp16 ----------------
__global__ __launch_bounds__(256) void cvt_kernel(const float* __restrict__ w0,
                                                  const float* __restrict__ w1,
                                                  const float* __restrict__ w2,
                                                  const float* __restrict__ w3) {
    const int sel = blockIdx.x >> 10;
    const float* src = (sel == 0) ? w0 : (sel == 1) ? w1 : (sel == 2) ? w2 : w3;
    __half* dst = g_w16[sel];
    size_t i = ((size_t)(blockIdx.x & 1023) * blockDim.x + threadIdx.x) * 4;
    float4 v = *(const float4*)(src + i);
    __half2* dd = (__half2*)(dst + i);
    dd[0] = __floats2half2_rn(v.x, v.y);
    dd[1] = __floats2half2_rn(v.z, v.w);
}

// ---------------- kernel 2: LayerNorm ----------------
__global__ __launch_bounds__(256) void ln_kernel(const float* __restrict__ x,
                                                 const float* __restrict__ gamma,
                                                 const float* __restrict__ beta) {
    __shared__ float redS[8], redQ[8];
    const int row = blockIdx.x;
    const int tid = threadIdx.x;
    float4 v = ((const float4*)(x + (size_t)row * NCH))[tid];
    float s = v.x + v.y + v.z + v.w;
    float q = v.x * v.x + v.y * v.y + v.z * v.z + v.w * v.w;
    #pragma unroll
    for (int o = 16; o > 0; o >>= 1) {
        s += __shfl_xor_sync(0xffffffffu, s, o);
        q += __shfl_xor_sync(0xffffffffu, q, o);
    }
    if ((tid & 31) == 0) { redS[tid >> 5] = s; redQ[tid >> 5] = q; }
    __syncthreads();
    float S = 0.f, Q = 0.f;
    #pragma unroll
    for (int i = 0; i < 8; i++) { S += redS[i]; Q += redQ[i]; }
    const float mu = S * (1.0f / NCH);
    const float var = Q * (1.0f / NCH) - mu * mu;
    const float rstd = rsqrtf(var + 1e-5f);
    float4 gv = ((const float4*)gamma)[tid];
    float4 bv = ((const float4*)beta)[tid];
    __half2 h0 = __floats2half2_rn((v.x - mu) * rstd * gv.x + bv.x,
                                   (v.y - mu) * rstd * gv.y + bv.y);
    __half2 h1 = __floats2half2_rn((v.z - mu) * rstd * gv.z + bv.z,
                                   (v.w - mu) * rstd * gv.w + bv.w);
    __half2* dst = (__half2*)(g_xn + (size_t)row * NCH + tid * 4);
    dst[0] = h0; dst[1] = h1;
}

// ---------------- kernel 3: HMMA GEMM, block 128x128, 8 warps (4x2 of 32x64) --
#define GP2 72
#define G_ST (128 * GP2)                       // per-operand stage halfs
#define GEMM_SMEM (6 * G_ST * 2)               // 3 stages x 2 operands = 110592 B

__global__ __launch_bounds__(256, 1) void gemm_hmma(float* __restrict__ outF, int qkv) {
    extern __shared__ __half sm[];
    __half* As[3] = { sm, sm + G_ST, sm + 2 * G_ST };
    __half* Bs[3] = { sm + 3 * G_ST, sm + 4 * G_ST, sm + 5 * G_ST };

    int wsel, bN;
    const __half* __restrict__ A;
    if (qkv) { wsel = blockIdx.x >> 3; bN = (blockIdx.x & 7) * 128; A = g_xn; }
    else     { wsel = 3;               bN = blockIdx.x * 128;       A = g_y;  }
    const __half* __restrict__ Bw = g_w16[wsel];
    const int bM = blockIdx.y * 128;

    const int tid = threadIdx.x;
    const int lane = tid & 31, warp = tid >> 5;
    const int wm = warp >> 1, wn = warp & 1;       // 4x2 warps, warp tile 32x64

    float acc[2][8][4];
    #pragma unroll
    for (int i = 0; i < 2; i++)
        #pragma unroll
        for (int j = 0; j < 8; j++)
            #pragma unroll
            for (int e = 0; e < 4; e++) acc[i][j][e] = 0.f;

    auto load_stage = [&](int slot, int k0) {
        #pragma unroll
        for (int i = 0; i < 4; i++) {
            const int idx = tid + i * 256;
            const int row = idx >> 3, c = idx & 7;
            cpa16(smem_u32(As[slot] + row * GP2 + c * 8),
                  A + (size_t)(bM + row) * NCH + k0 + c * 8);
            cpa16(smem_u32(Bs[slot] + row * GP2 + c * 8),
                  Bw + (size_t)(bN + row) * NCH + k0 + c * 8);
        }
        cpa_commit();
    };

    load_stage(0, 0);
    load_stage(1, 64);

    const int KT = NCH / 64;
    for (int kt = 0; kt < KT; kt++) {
        if (kt < KT - 1) cpa_wait1(); else cpa_wait0();
        __syncthreads();
        if (kt + 2 < KT) load_stage((kt + 2) % 3, (kt + 2) * 64);

        const __half* as = As[kt % 3];
        const __half* bs = Bs[kt % 3];
        #pragma unroll
        for (int kk = 0; kk < 64; kk += 16) {
            const int cA = kk + 8 * (lane >> 4);
            uint32_t af[2][4];
            const int rA = wm * 32 + (lane & 15);
            #pragma unroll
            for (int mt = 0; mt < 2; mt++)
                ldm_x4(af[mt], as + (rA + mt * 16) * GP2 + cA);
            uint32_t bf[8][2];
            const int rB = wn * 64 + (lane & 15);
            #pragma unroll
            for (int p = 0; p < 4; p++) {
                uint32_t t4[4];
                ldm_x4(t4, bs + (rB + p * 16) * GP2 + cA);
                bf[p * 2][0]     = t4[0]; bf[p * 2][1]     = t4[2];
                bf[p * 2 + 1][0] = t4[1]; bf[p * 2 + 1][1] = t4[3];
            }
            #pragma unroll
            for (int mt = 0; mt < 2; mt++)
                #pragma unroll
                for (int nt = 0; nt < 8; nt++)
                    mma_16816(acc[mt][nt], af[mt], bf[nt]);
        }
    }

    #pragma unroll
    for (int mt = 0; mt < 2; mt++) {
        #pragma unroll
        for (int nt = 0; nt < 8; nt++) {
            const int r0 = bM + wm * 32 + mt * 16 + (lane >> 2);
            const int c0 = bN + wn * 64 + nt * 8 + (lane & 3) * 2;
            const float* v = acc[mt][nt];
            #pragma unroll
            for (int half_ : {0, 1}) {
                const int r = r0 + half_ * 8;
                const float v0 = v[half_ * 2], v1 = v[half_ * 2 + 1];
                const int b = r >> 11, t = r & 2047;
                if (wsel == 3) {
                    float2* dst = (float2*)(outF + (size_t)r * NCH + c0);
                    *dst = make_float2(v0, v1);
                } else if (wsel == 2) {
                    const int h = c0 >> 6, d = c0 & 63;
                    __half* base = g_vT + (((size_t)b * NHEAD + h) * NHD + d) * NTOK + t;
                    base[0]    = __float2half_rn(v0);
                    base[NTOK] = __float2half_rn(v1);
                } else {
                    const int h = c0 >> 6, d = c0 & 63;
                    __half* base = ((wsel == 0) ? g_q : g_k) +
                                   (((size_t)b * NHEAD + h) * NTOK + t) * NHD + d;
                    *(__half2*)base = __floats2half2_rn(v0, v1);
                }
            }
        }
    }
}

// ---------------- kernel 4: flash attention (R10 config: Br=64, Bc=64) ---------
#define AP 72   // smem pitch (144B) for 64-wide fp16 tiles, conflict-free ldmatrix

__global__ __launch_bounds__(128) void attn_kernel() {
    const int qt = gridDim.x - 1 - blockIdx.x;   // heaviest blocks first
    const int bh = blockIdx.y;                   // 0..63
    const int tid = threadIdx.x;
    const int lane = tid & 31, warp = tid >> 5;
    const int q0 = qt * 64;

    const __half* __restrict__ Qg = g_q  + (size_t)bh * NTOK * NHD;
    const __half* __restrict__ Kg = g_k  + (size_t)bh * NTOK * NHD;
    const __half* __restrict__ Vg = g_vT + (size_t)bh * NHD * NTOK;

    __shared__ __half Qs[64 * AP];
    __shared__ __half Ks[2][64 * AP];
    __shared__ __half Vs[2][64 * AP];

    // prologue: Q tile + K/V tile 0 via cp.async (one group)
    #pragma unroll
    for (int i = 0; i < 4; i++) {
        const int idx = tid + i * 128;
        const int r = idx >> 3, ch = (idx & 7) * 8;
        cpa16(smem_u32(&Qs[r * AP + ch]),    Qg + (size_t)(q0 + r) * NHD + ch);
        cpa16(smem_u32(&Ks[0][r * AP + ch]), Kg + (size_t)r * NHD + ch);
        cpa16(smem_u32(&Vs[0][r * AP + ch]), Vg + (size_t)r * NTOK + ch);
    }
    cpa_commit();
    cpa_wait0();
    __syncthreads();

    // Q fragments, pre-scaled by head_dim^-0.5 * log2(e) => softmax in base 2
    uint32_t qf[4][4];
    {
        const int rA = warp * 16 + (lane & 15);
        const int cA = 8 * (lane >> 4);
        const __half2 sc = __float2half2_rn(0.125f * 1.44269504f);
        #pragma unroll
        for (int kc = 0; kc < 4; kc++) {
            ldm_x4(qf[kc], &Qs[rA * AP + kc * 16 + cA]);
            #pragma unroll
            for (int e = 0; e < 4; e++) {
                __half2 h = *reinterpret_cast<__half2*>(&qf[kc][e]);
                h = __hmul2(h, sc);
                qf[kc][e] = *reinterpret_cast<uint32_t*>(&h);
            }
        }
    }

    float m0 = negInf(), m1 = negInf();
    float l0 = 0.f, l1 = 0.f;
    float o[8][4];
    #pragma unroll
    for (int nt = 0; nt < 8; nt++)
        #pragma unroll
        for (int e = 0; e < 4; e++) o[nt][e] = 0.f;

    const int rP = lane & 15;            // x4 ldmatrix row within 16-row pair
    const int cP = 8 * (lane >> 4);      // k-half select

    for (int j = 0; j <= qt; j++) {
        const int buf = j & 1;
        if (j < qt) {
            const int nb = buf ^ 1;
            #pragma unroll
            for (int i = 0; i < 4; i++) {
                const int idx = tid + i * 128;
                const int r = idx >> 3, ch = (idx & 7) * 8;
                cpa16(smem_u32(&Ks[nb][r * AP + ch]),
                      Kg + (size_t)((j + 1) * 64 + r) * NHD + ch);
                cpa16(smem_u32(&Vs[nb][r * AP + ch]),
                      Vg + (size_t)r * NTOK + (j + 1) * 64 + ch);
            }
            cpa_commit();
        }

        // S = (Q*scale) @ K^T : 16x64 per warp; K frags via x4 over 16-row pairs
        float s[8][4];
        #pragma unroll
        for (int nt = 0; nt < 8; nt++)
            #pragma unroll
            for (int e = 0; e < 4; e++) s[nt][e] = 0.f;
        #pragma unroll
        for (int kc = 0; kc < 4; kc++) {
            #pragma unroll
            for (int p = 0; p < 4; p++) {
                uint32_t t4[4];
                ldm_x4(t4, &Ks[buf][(p * 16 + rP) * AP + kc * 16 + cP]);
                uint32_t be[2] = { t4[0], t4[2] };
                uint32_t bo[2] = { t4[1], t4[3] };
                mma_16816(s[p * 2],     qf[kc], be);
                mma_16816(s[p * 2 + 1], qf[kc], bo);
            }
        }

        // causal mask on the diagonal tile
        if (j == qt) {
            const int rl = warp * 16 + (lane >> 2);
            const int cb = (lane & 3) * 2;
            #pragma unroll
            for (int nt = 0; nt < 8; nt++) {
                const int c0 = nt * 8 + cb;
                if (c0     > rl)     s[nt][0] = -1e30f;
                if (c0 + 1 > rl)     s[nt][1] = -1e30f;
                if (c0     > rl + 8) s[nt][2] = -1e30f;
                if (c0 + 1 > rl + 8) s[nt][3] = -1e30f;
            }
        }

        // online softmax in base 2 (rows r and r+8 per lane-group)
        float mx0 = -3.0e38f, mx1 = -3.0e38f;
        #pragma unroll
        for (int nt = 0; nt < 8; nt++) {
            mx0 = fmaxf(mx0, fmaxf(s[nt][0], s[nt][1]));
            mx1 = fmaxf(mx1, fmaxf(s[nt][2], s[nt][3]));
        }
        mx0 = fmaxf(mx0, __shfl_xor_sync(0xffffffffu, mx0, 1));
        mx0 = fmaxf(mx0, __shfl_xor_sync(0xffffffffu, mx0, 2));
        mx1 = fmaxf(mx1, __shfl_xor_sync(0xffffffffu, mx1, 1));
        mx1 = fmaxf(mx1, __shfl_xor_sync(0xffffffffu, mx1, 2));
        const float mn0 = fmaxf(m0, mx0), mn1 = fmaxf(m1, mx1);
        const float cor0 = ex2(m0 - mn0), cor1 = ex2(m1 - mn1);
        m0 = mn0; m1 = mn1;
        float sum0 = 0.f, sum1 = 0.f;
        #pragma unroll
        for (int nt = 0; nt < 8; nt++) {
            s[nt][0] = ex2(s[nt][0] - mn0); sum0 += s[nt][0];
            s[nt][1] = ex2(s[nt][1] - mn0); sum0 += s[nt][1];
            s[nt][2] = ex2(s[nt][2] - mn1); sum1 += s[nt][2];
            s[nt][3] = ex2(s[nt][3] - mn1); sum1 += s[nt][3];
        }
        sum0 += __shfl_xor_sync(0xffffffffu, sum0, 1);
        sum0 += __shfl_xor_sync(0xffffffffu, sum0, 2);
        sum1 += __shfl_xor_sync(0xffffffffu, sum1, 1);
        sum1 += __shfl_xor_sync(0xffffffffu, sum1, 2);
        l0 = l0 * cor0 + sum0;
        l1 = l1 * cor1 + sum1;
        #pragma unroll
        for (int nt = 0; nt < 8; nt++) {
            o[nt][0] *= cor0; o[nt][1] *= cor0;
            o[nt][2] *= cor1; o[nt][3] *= cor1;
        }

        // P fragments directly from S accumulators
        uint32_t pf[4][4];
        #pragma unroll
        for (int kc = 0; kc < 4; kc++) {
            pf[kc][0] = f2h2u(s[2 * kc][0],     s[2 * kc][1]);
            pf[kc][1] = f2h2u(s[2 * kc][2],     s[2 * kc][3]);
            pf[kc][2] = f2h2u(s[2 * kc + 1][0], s[2 * kc + 1][1]);
            pf[kc][3] = f2h2u(s[2 * kc + 1][2], s[2 * kc + 1][3]);
        }

        // O += P @ V ; V frags via x4 over 16-row pairs
        #pragma unroll
        for (int kc = 0; kc < 4; kc++) {
            #pragma unroll
            for (int p = 0; p < 4; p++) {
                uint32_t t4[4];
                ldm_x4(t4, &Vs[buf][(p * 16 + rP) * AP + kc * 16 + cP]);
                uint32_t be[2] = { t4[0], t4[2] };
                uint32_t bo[2] = { t4[1], t4[3] };
                mma_16816(o[p * 2],     pf[kc], be);
                mma_16816(o[p * 2 + 1], pf[kc], bo);
            }
        }

        if (j < qt) {
            cpa_wait0();
            __syncthreads();
        }
    }

    // finalize
    const int b = bh >> 4, h = bh & 15;
    const int trow = q0 + warp * 16 + (lane >> 2);
    const float inv0 = 1.0f / l0, inv1 = 1.0f / l1;
    #pragma unroll
    for (int nt = 0; nt < 8; nt++) {
        const int col = h * 64 + nt * 8 + (lane & 3) * 2;
        const size_t base = (size_t)(b * NTOK + trow) * NCH + col;
        *(__half2*)(g_y + base) = __floats2half2_rn(o[nt][0] * inv0, o[nt][1] * inv0);
        *(__half2*)(g_y + base + (size_t)8 * NCH) =
            __floats2half2_rn(o[nt][2] * inv1, o[nt][3] * inv1);
    }
}

// ---------------- launch ----------------
extern "C" void kernel_launch(void* const* d_in, const int* in_sizes, int n_in,
                              void* d_out, int out_size) {
    (void)in_sizes; (void)n_in; (void)out_size;
    const float* x     = (const float*)d_in[0];
    const float* gamma = (const float*)d_in[1];
    const float* beta  = (const float*)d_in[2];

    cudaFuncSetAttribute(gemm_hmma, cudaFuncAttributeMaxDynamicSharedMemorySize, GEMM_SMEM);

    cvt_kernel<<<4096, 256>>>((const float*)d_in[3], (const float*)d_in[4],
                              (const float*)d_in[5], (const float*)d_in[6]);

    ln_kernel<<<NROWS, 256>>>(x, gamma, beta);

    gemm_hmma<<<dim3(24, 64), 256, GEMM_SMEM>>>(nullptr, 1);        // fused Q/K/V

    attn_kernel<<<dim3(NTOK / 64, NBATCH * NHEAD), 128>>>();

    gemm_hmma<<<dim3(8, 64), 256, GEMM_SMEM>>>((float*)d_out, 0);   // output proj
}